// round 2
// baseline (speedup 1.0000x reference)
#include <cuda_runtime.h>
#include <math.h>

#define S_LEN 512
#define B_SZ  256
#define E_DIM 128
#define H_DIM 256

// 134 MB scratch for precomputed input projections (device global: no runtime alloc).
static __device__ float g_xproj[(size_t)S_LEN * B_SZ * H_DIM];

// ---------------------------------------------------------------------------
// Kernel 1: fused embedding gather + input projection + bias
//   g_xproj[m][h] = sum_e emb[X[m]][e] * W_ih[h][e] + b_ih[h] + b_hh[h]
// where m = s*B + b (X is [S][B] row-major, so X[m] is direct).
// M-tile = 32 rows, N = 256 (all of H), K = 128.
// Smem: W_ih transposed [k][n] (128 KB) + gathered A tile [m][kq] float4 (16 KB).
// ---------------------------------------------------------------------------
__global__ void __launch_bounds__(256) xproj_kernel(
    const int* __restrict__ X, const float* __restrict__ emb,
    const float* __restrict__ W_ih, const float* __restrict__ b_ih,
    const float* __restrict__ b_hh)
{
    extern __shared__ float sm[];
    float*  Ws  = sm;                          // [128][256] = 32768 floats
    float4* As4 = (float4*)(sm + 128 * 256);   // [32][32] float4 = 16 KB
    __shared__ int ids[32];

    const int t  = threadIdx.x;
    const int m0 = blockIdx.x * 32;
    const int n  = t;

    if (t < 32) ids[t] = X[m0 + t];

    // Stage W_ih transposed: Ws[k][n] = W_ih[n][k]. Thread t owns row n=t.
    {
        const float4* wr = (const float4*)(W_ih + (size_t)n * E_DIM);
#pragma unroll
        for (int kq = 0; kq < 32; kq++) {
            float4 f = wr[kq];
            Ws[(4 * kq + 0) * 256 + n] = f.x;
            Ws[(4 * kq + 1) * 256 + n] = f.y;
            Ws[(4 * kq + 2) * 256 + n] = f.z;
            Ws[(4 * kq + 3) * 256 + n] = f.w;
        }
    }
    __syncthreads();  // ids visible

    // Gather A: As4[m][kq] = emb[ids[m]][4kq..4kq+3]
#pragma unroll
    for (int r = 0; r < 4; r++) {
        int p = t + 256 * r;          // 0..1023
        int m = p >> 5, kq = p & 31;
        As4[m * 32 + kq] = ((const float4*)(emb + (size_t)ids[m] * E_DIM))[kq];
    }
    __syncthreads();  // A and W staged

    float acc[32];
#pragma unroll
    for (int m = 0; m < 32; m++) acc[m] = 0.0f;

    for (int kq = 0; kq < 32; kq++) {
        float w0 = Ws[(4 * kq + 0) * 256 + n];
        float w1 = Ws[(4 * kq + 1) * 256 + n];
        float w2 = Ws[(4 * kq + 2) * 256 + n];
        float w3 = Ws[(4 * kq + 3) * 256 + n];
#pragma unroll
        for (int m = 0; m < 32; m++) {
            float4 a = As4[m * 32 + kq];   // broadcast
            acc[m] = fmaf(a.x, w0, fmaf(a.y, w1, fmaf(a.z, w2, fmaf(a.w, w3, acc[m]))));
        }
    }

    const float bias = b_ih[n] + b_hh[n];
#pragma unroll
    for (int m = 0; m < 32; m++)
        g_xproj[(size_t)(m0 + m) * H_DIM + n] = acc[m] + bias;
}

// ---------------------------------------------------------------------------
// Kernel 2: full 512-step recurrence + fused log_softmax.
//   h_new[i] = tanh(xp[s][b][i] + sum_j W_hh[i][j] * h[j])
// One CTA = 2 batch rows, 256 threads (thread i = output element i).
// W_hh split: j in [0,128) in smem (Ws4[jq][i], conflict-free float4 LDS);
//             j in [128,256) in registers (Wreg[32] float4 per thread).
// ---------------------------------------------------------------------------
__global__ void __launch_bounds__(256, 1) rnn_kernel(
    const float* __restrict__ W_hh, float* __restrict__ out)
{
    extern __shared__ float sm[];
    float* Wsh = sm;              // 32768 floats (128 KB)
    float* h0s = sm + 32768;      // 256
    float* h1s = h0s + 256;       // 256
    float* red = h1s + 256;       // 256
    float4* Ws4 = (float4*)Wsh;

    const int i  = threadIdx.x;
    const int b0 = blockIdx.x * 2;

    // Load W_hh row i: first half to smem (transposed to [jq][i]), second half to regs.
    const float4* wrow = (const float4*)(W_hh + (size_t)i * H_DIM);
#pragma unroll
    for (int jq = 0; jq < 32; jq++) Ws4[jq * 256 + i] = wrow[jq];

    float4 Wreg[32];
#pragma unroll
    for (int jq = 0; jq < 32; jq++) Wreg[jq] = wrow[32 + jq];

    h0s[i] = 0.0f;
    h1s[i] = 0.0f;
    __syncthreads();

    const float4* h04 = (const float4*)h0s;
    const float4* h14 = (const float4*)h1s;
    const float* xpp = g_xproj + (size_t)b0 * H_DIM + i;  // step stride = B*H

    float xpA = xpp[0];
    float xpB = xpp[H_DIM];

    for (int s = 0; s < S_LEN; s++) {
        // Prefetch next step's xp under this step's compute.
        float xnA = 0.0f, xnB = 0.0f;
        if (s + 1 < S_LEN) {
            const float* nx = xpp + (size_t)(s + 1) * (B_SZ * H_DIM);
            xnA = nx[0];
            xnB = nx[H_DIM];
        }

        float accA[4] = {0.f, 0.f, 0.f, 0.f};
        float accB[4] = {0.f, 0.f, 0.f, 0.f};

        // smem half: j in [0,128)
#pragma unroll
        for (int jq = 0; jq < 32; jq++) {
            float4 w  = Ws4[jq * 256 + i];
            float4 hA = h04[jq];   // broadcast
            float4 hB = h14[jq];
            int r = jq & 3;
            accA[r] = fmaf(w.x, hA.x, fmaf(w.y, hA.y, fmaf(w.z, hA.z, fmaf(w.w, hA.w, accA[r]))));
            accB[r] = fmaf(w.x, hB.x, fmaf(w.y, hB.y, fmaf(w.z, hB.z, fmaf(w.w, hB.w, accB[r]))));
        }
        // register half: j in [128,256)
#pragma unroll
        for (int jq = 0; jq < 32; jq++) {
            float4 w  = Wreg[jq];
            float4 hA = h04[32 + jq];
            float4 hB = h14[32 + jq];
            int r = jq & 3;
            accA[r] = fmaf(w.x, hA.x, fmaf(w.y, hA.y, fmaf(w.z, hA.z, fmaf(w.w, hA.w, accA[r]))));
            accB[r] = fmaf(w.x, hB.x, fmaf(w.y, hB.y, fmaf(w.z, hB.z, fmaf(w.w, hB.w, accB[r]))));
        }

        float hnA = tanhf(xpA + ((accA[0] + accA[1]) + (accA[2] + accA[3])));
        float hnB = tanhf(xpB + ((accB[0] + accB[1]) + (accB[2] + accB[3])));

        __syncthreads();   // all reads of h done
        h0s[i] = hnA;
        h1s[i] = hnB;
        __syncthreads();   // new h visible

        xpA = xnA;
        xpB = xnB;
    }

    // Fused log_softmax over each of the 2 rows: x - max - log(sum exp(x - max))
    for (int b = 0; b < 2; b++) {
        float x = (b == 0) ? h0s[i] : h1s[i];

        red[i] = x;
        __syncthreads();
        for (int off = 128; off > 0; off >>= 1) {
            if (i < off) red[i] = fmaxf(red[i], red[i + off]);
            __syncthreads();
        }
        float mx = red[0];
        __syncthreads();

        red[i] = expf(x - mx);
        __syncthreads();
        for (int off = 128; off > 0; off >>= 1) {
            if (i < off) red[i] = red[i] + red[i + off];
            __syncthreads();
        }
        float lse = logf(red[0]);
        __syncthreads();

        out[(size_t)(b0 + b) * H_DIM + i] = x - mx - lse;
    }
}

extern "C" void kernel_launch(void* const* d_in, const int* in_sizes, int n_in,
                              void* d_out, int out_size)
{
    const int*   X    = (const int*)d_in[0];
    const float* emb  = (const float*)d_in[1];
    const float* W_ih = (const float*)d_in[2];
    const float* W_hh = (const float*)d_in[3];
    const float* b_ih = (const float*)d_in[4];
    const float* b_hh = (const float*)d_in[5];
    float* out = (float*)d_out;

    const int smem_xproj = (128 * 256 + 32 * 32 * 4) * 4;           // 147456 B
    const int smem_rnn   = (32768 + 256 + 256 + 256) * 4;           // 134144 B
    cudaFuncSetAttribute(xproj_kernel, cudaFuncAttributeMaxDynamicSharedMemorySize, smem_xproj);
    cudaFuncSetAttribute(rnn_kernel,   cudaFuncAttributeMaxDynamicSharedMemorySize, smem_rnn);

    // M = S*B = 131072 rows, 32 per CTA
    xproj_kernel<<<(S_LEN * B_SZ) / 32, 256, smem_xproj>>>(X, emb, W_ih, b_ih, b_hh);
    // 256 batch rows, 2 per CTA
    rnn_kernel<<<B_SZ / 2, 256, smem_rnn>>>(W_hh, out);
}

// round 3
// speedup vs baseline: 1.0059x; 1.0059x over previous
#include <cuda_runtime.h>
#include <math.h>
#include <string.h>

#define S_LEN 512
#define B_SZ  256
#define E_DIM 128
#define H_DIM 256

// Scratch for precomputed input projections (device global: no runtime alloc).
static __device__ float g_xproj[(size_t)S_LEN * B_SZ * H_DIM];

typedef unsigned long long ull;

// packed fp32x2 FMA: d = a*b + d (elementwise on (lo,hi) float pairs)
__device__ __forceinline__ void ffma2(ull& d, ull a, ull b) {
    asm("fma.rn.f32x2 %0, %1, %2, %0;" : "+l"(d) : "l"(a), "l"(b));
}
__device__ __forceinline__ ull dup2(float w) {
    ull p;
    asm("mov.b64 %0, {%1, %1};" : "=l"(p) : "f"(w));
    return p;
}
__device__ __forceinline__ float2 as_f2(ull v) {
    float2 f; memcpy(&f, &v, 8); return f;
}

// ---------------------------------------------------------------------------
// Kernel 1: fused embedding gather + input projection + bias (FFMA2 version)
//   g_xproj[m][n] = sum_k emb[X[m]][k] * W_ih[n][k] + b_ih[n] + b_hh[n]
// 256 threads, 32-row M tile. Thread n holds W_ih[n][:] in 128 registers.
// A staged transposed in smem: Asf[k][m] (m contiguous -> natural f32x2 pairs).
// ---------------------------------------------------------------------------
__global__ void __launch_bounds__(256) xproj_kernel(
    const int* __restrict__ X, const float* __restrict__ emb,
    const float* __restrict__ W_ih, const float* __restrict__ b_ih,
    const float* __restrict__ b_hh)
{
    __shared__ __align__(16) float Asf[E_DIM * 32];   // [k][m], 16 KB
    __shared__ int ids[32];

    const int t  = threadIdx.x;
    const int m0 = blockIdx.x * 32;
    const int n  = t;

    if (t < 32) ids[t] = X[m0 + t];

    // W_ih row n into registers (32 LDG.128)
    float Wreg[E_DIM];
    {
        const float4* wr = (const float4*)(W_ih + (size_t)n * E_DIM);
#pragma unroll
        for (int q = 0; q < 32; q++) {
            float4 f = wr[q];
            Wreg[4 * q + 0] = f.x; Wreg[4 * q + 1] = f.y;
            Wreg[4 * q + 2] = f.z; Wreg[4 * q + 3] = f.w;
        }
    }
    __syncthreads();  // ids visible

    // Stage A transposed: thread (m = t&31, c = t>>5) loads 4 consecutive
    // float4 chunks of emb row ids[m] (k-range 16c..16c+15) and scatters.
    // STS addresses = k*32 + m: lanes have consecutive m -> conflict-free.
    {
        const int m = t & 31, c = t >> 5;
        const float4* er = (const float4*)(emb + (size_t)ids[m] * E_DIM);
#pragma unroll
        for (int r = 0; r < 4; r++) {
            float4 f = er[c * 4 + r];
            int k = 16 * c + 4 * r;
            Asf[(k + 0) * 32 + m] = f.x;
            Asf[(k + 1) * 32 + m] = f.y;
            Asf[(k + 2) * 32 + m] = f.z;
            Asf[(k + 3) * 32 + m] = f.w;
        }
    }
    __syncthreads();

    ull acc[16];      // acc[j] holds outputs for rows (2j, 2j+1)
#pragma unroll
    for (int j = 0; j < 16; j++) acc[j] = 0ULL;

#pragma unroll 4
    for (int k = 0; k < E_DIM; k++) {
        ull wp = dup2(Wreg[k]);
        const ulonglong2* av = (const ulonglong2*)(Asf + k * 32);
#pragma unroll
        for (int mpp = 0; mpp < 8; mpp++) {
            ulonglong2 v = av[mpp];   // broadcast: rows 4mpp..4mpp+3 at this k
            ffma2(acc[2 * mpp + 0], v.x, wp);
            ffma2(acc[2 * mpp + 1], v.y, wp);
        }
    }

    const float bias = b_ih[n] + b_hh[n];
#pragma unroll
    for (int j = 0; j < 16; j++) {
        float2 f = as_f2(acc[j]);
        g_xproj[(size_t)(m0 + 2 * j + 0) * H_DIM + n] = f.x + bias;
        g_xproj[(size_t)(m0 + 2 * j + 1) * H_DIM + n] = f.y + bias;
    }
}

// ---------------------------------------------------------------------------
// Kernel 2: 512-step recurrence + fused log_softmax (FFMA2, ping-pong h,
// one barrier per step).
// 256 threads = one output each, 2 batch rows per CTA (grid 128).
// W_hh row i: j-quads 0..39 (160 j) in registers as ull pairs,
//             j-quads 40..63 (96 j) in smem (ulonglong2 per lane,
//             conflict-free).
// ---------------------------------------------------------------------------
__global__ void __launch_bounds__(256, 1) rnn_kernel(
    const float* __restrict__ W_hh, float* __restrict__ out)
{
    extern __shared__ __align__(16) float sm[];
    ulonglong2* Wsv = (ulonglong2*)sm;        // 24 quads * 256 * 16B = 96 KB
    float* hbuf = sm + 24 * 256 * 4;          // [2 bufs][2 rows][256]
    float* red  = hbuf + 2 * 2 * 256;         // 256 floats scratch

    const int i  = threadIdx.x;
    const int b0 = blockIdx.x * 2;

    // Load W_hh row i: quads 0..39 to regs (as ull pairs), 40..63 to smem.
    const ulonglong2* wr = (const ulonglong2*)(W_hh + (size_t)i * H_DIM);
    ull Wp[80];
#pragma unroll
    for (int q = 0; q < 40; q++) {
        ulonglong2 v = wr[q];
        Wp[2 * q] = v.x; Wp[2 * q + 1] = v.y;
    }
#pragma unroll
    for (int q = 0; q < 24; q++) Wsv[q * 256 + i] = wr[40 + q];

    hbuf[0 * 512 + 0 * 256 + i] = 0.0f;   // buf0 row A
    hbuf[0 * 512 + 1 * 256 + i] = 0.0f;   // buf0 row B
    __syncthreads();

    const float* xpp = g_xproj + (size_t)b0 * H_DIM + i;
    float xpA = xpp[0];
    float xpB = xpp[H_DIM];

    for (int s = 0; s < S_LEN; s++) {
        const float* hc = hbuf + (s & 1) * 512;
        const ulonglong2* hA4 = (const ulonglong2*)(hc);
        const ulonglong2* hB4 = (const ulonglong2*)(hc + 256);

        // Prefetch next step's xp under the compute.
        float xnA = 0.0f, xnB = 0.0f;
        if (s + 1 < S_LEN) {
            const float* nx = xpp + (size_t)(s + 1) * (B_SZ * H_DIM);
            xnA = nx[0];
            xnB = nx[H_DIM];
        }

        ull aA0 = 0ULL, aA1 = 0ULL, aB0 = 0ULL, aB1 = 0ULL;

        // Register half: j-quads 0..39
#pragma unroll
        for (int q = 0; q < 40; q++) {
            ulonglong2 ha = hA4[q];
            ulonglong2 hb = hB4[q];
            ffma2(aA0, Wp[2 * q],     ha.x);
            ffma2(aA1, Wp[2 * q + 1], ha.y);
            ffma2(aB0, Wp[2 * q],     hb.x);
            ffma2(aB1, Wp[2 * q + 1], hb.y);
        }
        // Smem half: j-quads 40..63
#pragma unroll
        for (int q = 0; q < 24; q++) {
            ulonglong2 wv = Wsv[q * 256 + i];
            ulonglong2 ha = hA4[40 + q];
            ulonglong2 hb = hB4[40 + q];
            ffma2(aA0, wv.x, ha.x);
            ffma2(aA1, wv.y, ha.y);
            ffma2(aB0, wv.x, hb.x);
            ffma2(aB1, wv.y, hb.y);
        }

        float2 fa0 = as_f2(aA0), fa1 = as_f2(aA1);
        float2 fb0 = as_f2(aB0), fb1 = as_f2(aB1);
        float hnA = tanhf(xpA + ((fa0.x + fa0.y) + (fa1.x + fa1.y)));
        float hnB = tanhf(xpB + ((fb0.x + fb0.y) + (fb1.x + fb1.y)));

        float* hn = hbuf + ((s + 1) & 1) * 512;
        hn[i]       = hnA;
        hn[256 + i] = hnB;
        __syncthreads();   // single barrier: next-buffer writes visible

        xpA = xnA;
        xpB = xnB;
    }

    // Final h is in buffer (S_LEN & 1) == 0.
    const float* hf = hbuf;

    // Fused log_softmax per row
    for (int b = 0; b < 2; b++) {
        float x = hf[b * 256 + i];

        red[i] = x;
        __syncthreads();
        for (int off = 128; off > 0; off >>= 1) {
            if (i < off) red[i] = fmaxf(red[i], red[i + off]);
            __syncthreads();
        }
        float mx = red[0];
        __syncthreads();

        red[i] = expf(x - mx);
        __syncthreads();
        for (int off = 128; off > 0; off >>= 1) {
            if (i < off) red[i] = red[i] + red[i + off];
            __syncthreads();
        }
        float lse = logf(red[0]);
        __syncthreads();

        out[(size_t)(b0 + b) * H_DIM + i] = x - mx - lse;
    }
}

extern "C" void kernel_launch(void* const* d_in, const int* in_sizes, int n_in,
                              void* d_out, int out_size)
{
    const int*   X    = (const int*)d_in[0];
    const float* emb  = (const float*)d_in[1];
    const float* W_ih = (const float*)d_in[2];
    const float* W_hh = (const float*)d_in[3];
    const float* b_ih = (const float*)d_in[4];
    const float* b_hh = (const float*)d_in[5];
    float* out = (float*)d_out;

    const int smem_rnn = (24 * 256 * 4 + 2 * 2 * 256 + 256) * 4;  // ~103 KB
    cudaFuncSetAttribute(rnn_kernel, cudaFuncAttributeMaxDynamicSharedMemorySize, smem_rnn);

    xproj_kernel<<<(S_LEN * B_SZ) / 32, 256>>>(X, emb, W_ih, b_ih, b_hh);
    rnn_kernel<<<B_SZ / 2, 256, smem_rnn>>>(W_hh, out);
}

// round 5
// speedup vs baseline: 1.0861x; 1.0797x over previous
#include <cuda_runtime.h>
#include <math.h>
#include <string.h>

#define S_LEN 512
#define B_SZ  256
#define E_DIM 128
#define H_DIM 256

// Scratch for precomputed input projections (device global: no runtime alloc).
static __device__ float g_xproj[(size_t)S_LEN * B_SZ * H_DIM];

typedef unsigned long long ull;

// packed fp32x2 FMA: d = a*b + d (elementwise on (lo,hi) float pairs)
__device__ __forceinline__ void ffma2(ull& d, ull a, ull b) {
    asm("fma.rn.f32x2 %0, %1, %2, %0;" : "+l"(d) : "l"(a), "l"(b));
}
__device__ __forceinline__ ull dup2(float w) {
    ull p;
    asm("mov.b64 %0, {%1, %1};" : "=l"(p) : "f"(w));
    return p;
}
__device__ __forceinline__ float2 as_f2(ull v) {
    float2 f; memcpy(&f, &v, 8); return f;
}

// ---------------------------------------------------------------------------
// Kernel 1: fused embedding gather + input projection + bias.
// 512 threads: thread (n = t&255, kh = t>>8) owns W_ih[n][64kh..64kh+64) in
// 64 registers, computes partial dot for 32 m-rows over its k-half.
// kh=1 writes partials to smem; kh=0 adds, biases, stores.
// ---------------------------------------------------------------------------
__global__ void __launch_bounds__(512, 1) xproj_kernel(
    const int* __restrict__ X, const float* __restrict__ emb,
    const float* __restrict__ W_ih, const float* __restrict__ b_ih,
    const float* __restrict__ b_hh)
{
    extern __shared__ __align__(16) float xsm[];
    float* Asf  = xsm;                 // [128][32] = 16 KB   (k-major, m contiguous)
    float* part = xsm + E_DIM * 32;    // [32][256] = 32 KB
    int*   ids  = (int*)(part + 32 * 256);  // 32 ints

    const int t  = threadIdx.x;
    const int n  = t & 255;
    const int kh = t >> 8;             // 0 or 1
    const int m0 = blockIdx.x * 32;

    if (t < 32) ids[t] = X[m0 + t];

    // W_ih[n][64kh .. 64kh+64) into 64 registers
    float Wreg[64];
    {
        const float4* wr = (const float4*)(W_ih + (size_t)n * E_DIM + 64 * kh);
#pragma unroll
        for (int q = 0; q < 16; q++) {
            float4 fv = wr[q];
            Wreg[4 * q + 0] = fv.x; Wreg[4 * q + 1] = fv.y;
            Wreg[4 * q + 2] = fv.z; Wreg[4 * q + 3] = fv.w;
        }
    }
    __syncthreads();   // ids visible

    // Stage A transposed: 32 rows x 32 float4 = 1024 float4, 2 per thread.
    // idx&31 = m (lane-consecutive -> conflict-free STS), idx>>5 = q.
#pragma unroll
    for (int rr = 0; rr < 2; rr++) {
        int idx = t + 512 * rr;
        int m = idx & 31, q = idx >> 5;
        float4 fv = ((const float4*)(emb + (size_t)ids[m] * E_DIM))[q];
        Asf[(4 * q + 0) * 32 + m] = fv.x;
        Asf[(4 * q + 1) * 32 + m] = fv.y;
        Asf[(4 * q + 2) * 32 + m] = fv.z;
        Asf[(4 * q + 3) * 32 + m] = fv.w;
    }
    __syncthreads();

    ull acc[16];
#pragma unroll
    for (int p = 0; p < 16; p++) acc[p] = 0ULL;

#pragma unroll 4
    for (int kl = 0; kl < 64; kl++) {
        ull wp = dup2(Wreg[kl]);
        const ulonglong2* av = (const ulonglong2*)(Asf + (64 * kh + kl) * 32);
#pragma unroll
        for (int p = 0; p < 8; p++) {
            ulonglong2 v = av[p];   // broadcast: m = 4p..4p+3
            ffma2(acc[2 * p + 0], v.x, wp);
            ffma2(acc[2 * p + 1], v.y, wp);
        }
    }

    if (kh == 1) {
#pragma unroll
        for (int p = 0; p < 16; p++) {
            float2 fv = as_f2(acc[p]);
            part[(2 * p + 0) * 256 + n] = fv.x;
            part[(2 * p + 1) * 256 + n] = fv.y;
        }
    }
    __syncthreads();
    if (kh == 0) {
        const float bias = b_ih[n] + b_hh[n];
#pragma unroll
        for (int p = 0; p < 16; p++) {
            float2 fv = as_f2(acc[p]);
            g_xproj[(size_t)(m0 + 2 * p + 0) * H_DIM + n] =
                fv.x + part[(2 * p + 0) * 256 + n] + bias;
            g_xproj[(size_t)(m0 + 2 * p + 1) * H_DIM + n] =
                fv.y + part[(2 * p + 1) * 256 + n] + bias;
        }
    }
}

// ---------------------------------------------------------------------------
// Kernel 2: 512-step recurrence + fused log_softmax.
// 512 threads, 2 batch rows per CTA (grid 128).
// Compute role: thread (io = t&127, jg = t>>7) handles outputs {io, io+128}
//   over j in [64jg, 64jg+64) for both rows: W[io][slice] in 64 regs,
//   W[io+128][slice] in smem (lane-distinct ulonglong2, conflict-free).
//   Each broadcast h-quad feeds 4 FFMA2.
// Finalize role: thread (r = t>>8, o = t&255) sums 4 partials + xp, tanh,
//   writes h in place. Two barriers per step.
// ---------------------------------------------------------------------------
__global__ void __launch_bounds__(512, 1) rnn_kernel(
    const float* __restrict__ W_hh, float* __restrict__ out)
{
    extern __shared__ __align__(16) float sm[];
    ulonglong2* Wsm = (ulonglong2*)sm;     // [16][512] ulonglong2 = 128 KB
    float* h    = sm + 32768;              // [2][256]
    float* part = h + 512;                 // [2][256][4]
    float* red  = part + 2048;             // [2][256]

    const int t  = threadIdx.x;
    const int io = t & 127;
    const int jg = t >> 7;                 // 0..3
    const int b0 = blockIdx.x * 2;

    // W row io -> regs, row io+128 -> smem; j slice [64jg, 64jg+64)
    {
        const ulonglong2* w1 = (const ulonglong2*)(W_hh + (size_t)(io + 128) * H_DIM + 64 * jg);
#pragma unroll
        for (int q = 0; q < 16; q++) Wsm[q * 512 + t] = w1[q];
    }
    ull Wp[32];
    {
        const ulonglong2* w0 = (const ulonglong2*)(W_hh + (size_t)io * H_DIM + 64 * jg);
#pragma unroll
        for (int q = 0; q < 16; q++) {
            ulonglong2 v = w0[q];
            Wp[2 * q] = v.x; Wp[2 * q + 1] = v.y;
        }
    }

    h[t] = 0.0f;                           // t<512 covers both rows
    __syncthreads();

    // finalize mapping
    const int fr = t >> 8, fo = t & 255;
    const float* xpp = g_xproj + (size_t)(b0 + fr) * H_DIM + fo;
    float xpv = xpp[0];

    const ulonglong2* hAq = (const ulonglong2*)(h + 64 * jg);
    const ulonglong2* hBq = (const ulonglong2*)(h + 256 + 64 * jg);

    for (int s = 0; s < S_LEN; s++) {
        float xnext = 0.0f;
        if (s + 1 < S_LEN) xnext = xpp[(size_t)(s + 1) * (B_SZ * H_DIM)];

        ull aA0 = 0ULL, aA1 = 0ULL, aB0 = 0ULL, aB1 = 0ULL;
#pragma unroll
        for (int q = 0; q < 16; q++) {
            ulonglong2 ha = hAq[q];             // broadcast
            ulonglong2 hb = hBq[q];             // broadcast
            ulonglong2 ws = Wsm[q * 512 + t];   // distinct, conflict-free
            ffma2(aA0, Wp[2 * q], ha.x); ffma2(aA0, Wp[2 * q + 1], ha.y);
            ffma2(aA1, ws.x,      ha.x); ffma2(aA1, ws.y,      ha.y);
            ffma2(aB0, Wp[2 * q], hb.x); ffma2(aB0, Wp[2 * q + 1], hb.y);
            ffma2(aB1, ws.x,      hb.x); ffma2(aB1, ws.y,      hb.y);
        }
        {
            float2 f0 = as_f2(aA0), f1 = as_f2(aA1);
            float2 f2 = as_f2(aB0), f3 = as_f2(aB1);
            part[(0 * 256 + io      ) * 4 + jg] = f0.x + f0.y;
            part[(0 * 256 + io + 128) * 4 + jg] = f1.x + f1.y;
            part[(1 * 256 + io      ) * 4 + jg] = f2.x + f2.y;
            part[(1 * 256 + io + 128) * 4 + jg] = f3.x + f3.y;
        }
        __syncthreads();   // partials visible; h reads done

        float4 p4 = *(const float4*)(part + t * 4);
        float hn = tanhf(((p4.x + p4.y) + (p4.z + p4.w)) + xpv);
        h[t] = hn;         // in-place update is safe: h no longer read this step
        __syncthreads();   // new h visible

        xpv = xnext;
    }

    // Fused log_softmax, both rows in parallel (row = fr, element = fo).
    float x = h[t];

    red[t] = x;
    __syncthreads();
    for (int off = 128; off > 0; off >>= 1) {
        if (fo < off) red[t] = fmaxf(red[t], red[t + off]);
        __syncthreads();
    }
    float mx = red[fr * 256];
    __syncthreads();

    red[t] = expf(x - mx);
    __syncthreads();
    for (int off = 128; off > 0; off >>= 1) {
        if (fo < off) red[t] = red[t] + red[t + off];
        __syncthreads();
    }
    float lse = logf(red[fr * 256]);

    out[(size_t)(b0 + fr) * H_DIM + fo] = x - mx - lse;
}

extern "C" void kernel_launch(void* const* d_in, const int* in_sizes, int n_in,
                              void* d_out, int out_size)
{
    const int*   X    = (const int*)d_in[0];
    const float* emb  = (const float*)d_in[1];
    const float* W_ih = (const float*)d_in[2];
    const float* W_hh = (const float*)d_in[3];
    const float* b_ih = (const float*)d_in[4];
    const float* b_hh = (const float*)d_in[5];
    float* out = (float*)d_out;

    const int smem_xproj = (E_DIM * 32 + 32 * 256) * 4 + 32 * 4;          // ~49.3 KB
    const int smem_rnn   = (32768 + 512 + 2048 + 512) * 4;                // 143.4 KB
    cudaFuncSetAttribute(xproj_kernel, cudaFuncAttributeMaxDynamicSharedMemorySize, smem_xproj);
    cudaFuncSetAttribute(rnn_kernel,   cudaFuncAttributeMaxDynamicSharedMemorySize, smem_rnn);

    xproj_kernel<<<(S_LEN * B_SZ) / 32, 512, smem_xproj>>>(X, emb, W_ih, b_ih, b_hh);
    rnn_kernel<<<B_SZ / 2, 512, smem_rnn>>>(W_hh, out);
}